// round 13
// baseline (speedup 1.0000x reference)
#include <cuda_runtime.h>
#include <cuda_fp16.h>
#include <cstdint>

// LSTMCell: gates = x@Wx + bx + h@Wh ; i,f,g,o -> (h_new, c_new)
// Virtual GEMM [8192,2048] x [2048,4096]^T (fp16, f32 acc), mma.sync.
// Pre-pass 1: g_Ah[8192,2048] fp16 = concat(x,h), K-major.
// Pre-pass 2: g_Wf = W packed in per-lane mma-fragment order (B never
//             touches smem in the main kernel; warps LDG.128 fragments
//             straight into registers). N rows gate-interleaved (n=j*4+g).
// Main: 128x128 tile, 64x32 warp tiles. A via cp.async 4-stage ring +
//       ldmatrix; B via direct fragment LDG with half-chunk double buffer.
//       Fused LSTM epilogue. 2 CTAs/SM.

#define B_DIM 8192
#define K_DIM 2048
#define N_DIM 4096
#define H_DIM 1024

#define BM 128
#define BN 128
#define BKH 64                    // K-chunk (halves)
#define NCHUNK (K_DIM / BKH)      // 32
#define THREADS 256
#define STAGES 4

#define A_STAGE_BYTES (BM * 128)                // 16384
#define OFF_BIAS 67584                          // after epilogue gsm 128*132*4
#define SMEM_TOTAL (OFF_BIAS + BN * 4)          // 68096
#define LDE 132

__device__ __half    g_Ah[(size_t)B_DIM * K_DIM];        // 32 MB
__device__ uint32_t  g_Wf[(size_t)N_DIM * K_DIM / 2];    // 16 MB packed frags

#define SW128(o) ((o) ^ (((o) >> 3) & 0x70))

__device__ __forceinline__ uint32_t smem_u32(const void* p) {
    uint32_t a;
    asm("{ .reg .u64 t; cvta.to.shared.u64 t, %1; cvt.u32.u64 %0, t; }"
        : "=r"(a) : "l"(p));
    return a;
}
__device__ __forceinline__ void cp16(uint32_t dst, const void* src) {
    asm volatile("cp.async.cg.shared.global [%0], [%1], 16;"
                 :: "r"(dst), "l"(src) : "memory");
}
#define CP_COMMIT() asm volatile("cp.async.commit_group;" ::: "memory")

__device__ __forceinline__ void ldsm4(uint32_t& r0, uint32_t& r1,
                                      uint32_t& r2, uint32_t& r3, uint32_t a) {
    asm volatile("ldmatrix.sync.aligned.m8n8.x4.shared.b16 {%0,%1,%2,%3}, [%4];"
                 : "=r"(r0), "=r"(r1), "=r"(r2), "=r"(r3) : "r"(a));
}

// ------------------------------------------------------------- pre-passes
__global__ void conv_A(const float* __restrict__ x, const float* __restrict__ h) {
    int i = blockIdx.x * blockDim.x + threadIdx.x;
    int row = i >> 8;
    int col = (i & 255) * 8;
    const float* src = (col < 1024) ? (x + (size_t)row * 1024 + col)
                                    : (h + (size_t)row * 1024 + (col - 1024));
    float4 v0 = ((const float4*)src)[0];
    float4 v1 = ((const float4*)src)[1];
    __half2 p[4];
    p[0] = __floats2half2_rn(v0.x, v0.y);
    p[1] = __floats2half2_rn(v0.z, v0.w);
    p[2] = __floats2half2_rn(v1.x, v1.y);
    p[3] = __floats2half2_rn(v1.z, v1.w);
    *(uint4*)(g_Ah + (size_t)row * K_DIM + col) = *(uint4*)p;
}

// Pack W into per-lane fragment order.
// Fragment spec (m16n8k16, B col-major KxN): lane l, n8-tile nt, k16-step:
//   b0 = {B[k=(l&3)*2+0, n=base+(l>>2)], B[k+1, n]},  b1 = {B[k+8, n], B[k+9, n]}
// Packed block per (nblk, kt, h, wn): [q 0..3][lane 0..31][e 0..3] u32,
//   flat t = q*4+e = ksl*8 + nt*2 + r.
__global__ void pack_W(const float* __restrict__ Wx, const float* __restrict__ Wh) {
    __shared__ __half t[128][33];
    const int n0 = blockIdx.x * 32;       // 32 consecutive n (gate-interleaved)
    const int k0 = blockIdx.y * 128;
    const int tid = threadIdx.x;

    // load 128k x 32n, coalesced in 8-float runs
    #pragma unroll
    for (int i = 0; i < 16; i++) {
        int idx = tid + i * 256;          // 0..4095
        int r8 = idx & 7;
        int g  = (idx >> 3) & 3;
        int k  = idx >> 5;                // 0..127
        int col = g * 1024 + (n0 >> 2) + r8;
        int kg = k0 + k;
        float v = (kg < 1024) ? Wx[(size_t)kg * N_DIM + col]
                              : Wh[(size_t)(kg - 1024) * N_DIM + col];
        t[k][r8 * 4 + g] = __float2half_rn(v);
    }
    __syncthreads();

    // emit packed u32s (coalesced)
    const int nblk = blockIdx.x >> 2;
    const int wn   = blockIdx.x & 3;
    #pragma unroll
    for (int i = 0; i < 8; i++) {
        int o = tid + i * 256;            // 0..2047
        int e    = o & 3;
        int lane = (o >> 2) & 31;
        int q    = (o >> 7) & 3;
        int b32  = o >> 9;                // which 32-k group (0..3)
        int tq  = q * 4 + e;
        int ksl = tq >> 3;
        int nt  = (tq >> 1) & 3;
        int r   = tq & 1;
        int nl   = nt * 8 + (lane >> 2);
        int kloc = ksl * 16 + (lane & 3) * 2 + r * 8;
        int k32  = b32 * 32 + kloc;
        uint32_t lo = __half_as_ushort(t[k32][nl]);
        uint32_t hi = __half_as_ushort(t[k32 + 1][nl]);
        int kt = (k0 + b32 * 32) >> 6;
        int h  = b32 & 1;
        size_t addr = ((((size_t)nblk * 32 + kt) * 2 + h) * 4 + wn) * 512
                      + q * 128 + lane * 4 + e;
        g_Wf[addr] = lo | (hi << 16);
    }
}

// ------------------------------------------------------------- main kernel
__global__ __launch_bounds__(THREADS, 2)
void lstm_main(const float* __restrict__ cin, const float* __restrict__ bx,
               float* __restrict__ out)
{
    extern __shared__ char smem[];
    const uint32_t sb = smem_u32(smem);
    const int tid  = threadIdx.x;
    const int lane = tid & 31;
    const int warp = tid >> 5;
    const int wm   = warp >> 2;       // 0..1  (64-row slab)
    const int wn   = warp & 3;        // 0..3  (32-col slab)
    const int m0 = blockIdx.y * BM;
    const int n0 = blockIdx.x * BN;
    const int jt0 = n0 >> 2;

    const int r0 = tid >> 3, c8 = tid & 7;

    const __half* Agm = g_Ah + (size_t)m0 * K_DIM;
    const uint32_t* __restrict__ Bp =
        g_Wf + (size_t)blockIdx.x * 131072 + wn * 512 + lane * 4;

    float acc[4][4][4];
    #pragma unroll
    for (int i = 0; i < 4; i++)
        #pragma unroll
        for (int j = 0; j < 4; j++)
            #pragma unroll
            for (int k = 0; k < 4; k++) acc[i][j][k] = 0.0f;

    // A prologue: chunks 0..2 into 4-stage ring
    #pragma unroll
    for (int pc = 0; pc < 3; pc++) {
        uint32_t Ab = sb + pc * A_STAGE_BYTES;
        #pragma unroll
        for (int i = 0; i < 4; i++) {
            int row = r0 + 32 * i;
            uint32_t o = (uint32_t)row * 128 + c8 * 16;
            cp16(Ab + SW128(o), Agm + (size_t)row * K_DIM + pc * BKH + c8 * 8);
        }
        CP_COMMIT();
    }

    // B prologue: fragments for (kt=0, h=0) into bf[1]
    uint32_t bf[2][16];
    #pragma unroll
    for (int q = 0; q < 4; q++)
        *(uint4*)&bf[1][q * 4] = *(const uint4*)(Bp + q * 128);
    Bp += 2048;

    const int qq = lane >> 3;
    const int rr = lane & 7;

    for (int kt = 0; kt < NCHUNK; kt++) {
        if (kt + 2 < NCHUNK)
            asm volatile("cp.async.wait_group 2;" ::: "memory");
        else if (kt + 1 < NCHUNK)
            asm volatile("cp.async.wait_group 1;" ::: "memory");
        else
            asm volatile("cp.async.wait_group 0;" ::: "memory");
        __syncthreads();

        if (kt + 3 < NCHUNK) {
            const int s = (kt + 3) & (STAGES - 1);
            uint32_t Ab = sb + s * A_STAGE_BYTES;
            const int ko = (kt + 3) * BKH;
            #pragma unroll
            for (int i = 0; i < 4; i++) {
                int row = r0 + 32 * i;
                uint32_t o = (uint32_t)row * 128 + c8 * 16;
                cp16(Ab + SW128(o), Agm + (size_t)row * K_DIM + ko + c8 * 8);
            }
            CP_COMMIT();
        }

        const uint32_t Ab = sb + (kt & (STAGES - 1)) * A_STAGE_BYTES;

        #pragma unroll
        for (int h = 0; h < 2; h++) {
            // load next half's B fragments into bf[h]; consume bf[h^1]
            if (kt + 1 < NCHUNK || h == 0) {
                #pragma unroll
                for (int q = 0; q < 4; q++)
                    *(uint4*)&bf[h][q * 4] = *(const uint4*)(Bp + q * 128);
                Bp += 2048;
            }
            #pragma unroll
            for (int ksl = 0; ksl < 2; ksl++) {
                const int ks = h * 2 + ksl;
                #pragma unroll
                for (int mt = 0; mt < 4; mt++) {
                    uint32_t a0, a1, a2, a3;
                    int row = wm * 64 + mt * 16 + (qq & 1) * 8 + rr;
                    uint32_t o = (uint32_t)row * 128 + ks * 32 + (qq >> 1) * 16;
                    ldsm4(a0, a1, a2, a3, Ab + SW128(o));
                    #pragma unroll
                    for (int nt = 0; nt < 4; nt++) {
                        const uint32_t b0 = bf[h ^ 1][ksl * 8 + nt * 2];
                        const uint32_t b1 = bf[h ^ 1][ksl * 8 + nt * 2 + 1];
                        asm volatile(
                            "mma.sync.aligned.m16n8k16.row.col.f32.f16.f16.f32 "
                            "{%0,%1,%2,%3}, {%4,%5,%6,%7}, {%8,%9}, {%0,%1,%2,%3};"
                            : "+f"(acc[mt][nt][0]), "+f"(acc[mt][nt][1]),
                              "+f"(acc[mt][nt][2]), "+f"(acc[mt][nt][3])
                            : "r"(a0), "r"(a1), "r"(a2), "r"(a3),
                              "r"(b0), "r"(b1));
                    }
                }
            }
        }
    }
    __syncthreads();   // retire last compute before smem reuse

    // -- epilogue: regroup via smem, fuse LSTM ----------------------------
    float* gsm = (float*)smem;        // [128][LDE]
    {
        const int gr = lane >> 2, gc = lane & 3;
        #pragma unroll
        for (int mt = 0; mt < 4; mt++)
            #pragma unroll
            for (int nt = 0; nt < 4; nt++) {
                int row = wm * 64 + mt * 16 + gr;
                int col = wn * 32 + nt * 8 + gc * 2;
                *(float2*)&gsm[row * LDE + col] =
                    make_float2(acc[mt][nt][0], acc[mt][nt][1]);
                *(float2*)&gsm[(row + 8) * LDE + col] =
                    make_float2(acc[mt][nt][2], acc[mt][nt][3]);
            }
    }
    float* bsm = (float*)(smem + OFF_BIAS);
    if (tid < BN)
        bsm[tid] = bx[(tid & 3) * 1024 + jt0 + (tid >> 2)];
    __syncthreads();

    float* outh = out;
    float* outc = out + (size_t)B_DIM * H_DIM;
    #pragma unroll
    for (int i = 0; i < 16; i++) {
        int o   = tid + i * THREADS;   // 0..4095 = 128 rows x 32 units
        int u   = o & 31;
        int row = o >> 5;
        float4 g4 = *(const float4*)&gsm[row * LDE + u * 4];
        float4 b4 = *(const float4*)&bsm[u * 4];
        float gi = g4.x + b4.x;
        float gf = g4.y + b4.y;
        float gg = g4.z + b4.z;
        float go = g4.w + b4.w;
        float iv = 1.0f / (1.0f + __expf(-gi));
        float fv = 1.0f / (1.0f + __expf(-gf));
        float gv = tanhf(gg);
        float ov = 1.0f / (1.0f + __expf(-go));
        size_t gidx = (size_t)(m0 + row) * H_DIM + jt0 + u;
        float cn = fv * cin[gidx] + iv * gv;
        outh[gidx] = ov * tanhf(cn);
        outc[gidx] = cn;
    }
}

// ------------------------------------------------------------- launch
extern "C" void kernel_launch(void* const* d_in, const int* in_sizes, int n_in,
                              void* d_out, int out_size)
{
    const float* x  = (const float*)d_in[0];
    const float* h  = (const float*)d_in[1];
    const float* c  = (const float*)d_in[2];
    const float* Wx = (const float*)d_in[3];
    const float* bx = (const float*)d_in[4];
    const float* Wh = (const float*)d_in[5];
    float* out = (float*)d_out;

    conv_A<<<(B_DIM * K_DIM / 8) / 256, 256>>>(x, h);
    pack_W<<<dim3(N_DIM / 32, K_DIM / 128), 256>>>(Wx, Wh);

    cudaFuncSetAttribute(lstm_main,
                         cudaFuncAttributeMaxDynamicSharedMemorySize, SMEM_TOTAL);
    dim3 grid(N_DIM / BN, B_DIM / BM);   // (32, 64)
    lstm_main<<<grid, THREADS, SMEM_TOTAL>>>(c, bx, out);
}

// round 17
// speedup vs baseline: 1.0563x; 1.0563x over previous
#include <cuda_runtime.h>
#include <cuda_fp16.h>
#include <cstdint>

// LSTMCell: gates = x@Wx + bx + h@Wh ; i,f,g,o -> (h_new, c_new)
// Virtual GEMM [8192,2048] x [2048,4096]^T (fp16, f32 acc), mma.sync.
// prep (one kernel, grid-split):
//   part 1: g_Ah[8192,2048] fp16 = concat(x,h), K-major.
//   part 2: g_Wt[4096,2048] fp16 = W^T, K-major, gate-interleaved rows
//           (row j*4+g) so the LSTM epilogue fuses per CTA.
// Main: 128x128 tile, 64x32 warp tiles, cp.async 3-stage ring, single
//       barrier per chunk, ldmatrix.x4 with ks-level A-fragment register
//       double-buffering, mma.sync.m16n8k16, fused LSTM epilogue. 2 CTA/SM.

#define B_DIM 8192
#define K_DIM 2048
#define N_DIM 4096
#define H_DIM 1024

#define BM 128
#define BN 128
#define BKH 64                    // K-chunk in halves = 128 B rows
#define NCHUNK (K_DIM / BKH)      // 32
#define THREADS 256
#define STAGES 3

#define STAGE_BYTES (BM * 128 + BN * 128)       // 32768
#define OFF_BIAS (STAGES * STAGE_BYTES)         // 98304
#define SMEM_TOTAL (OFF_BIAS + BN * 4)          // 98816
#define LDE 132                                  // epilogue row pitch (floats)

__device__ __half g_Ah[(size_t)B_DIM * K_DIM];  // 32 MB
__device__ __half g_Wt[(size_t)N_DIM * K_DIM];  // 16 MB

#define SW128(o) ((o) ^ (((o) >> 3) & 0x70))

__device__ __forceinline__ uint32_t smem_u32(const void* p) {
    uint32_t a;
    asm("{ .reg .u64 t; cvta.to.shared.u64 t, %1; cvt.u32.u64 %0, t; }"
        : "=r"(a) : "l"(p));
    return a;
}
__device__ __forceinline__ void cp16(uint32_t dst, const void* src) {
    asm volatile("cp.async.cg.shared.global [%0], [%1], 16;"
                 :: "r"(dst), "l"(src) : "memory");
}
#define CP_COMMIT() asm volatile("cp.async.commit_group;" ::: "memory")

__device__ __forceinline__ void ldsm4(uint32_t& r0, uint32_t& r1,
                                      uint32_t& r2, uint32_t& r3, uint32_t a) {
    asm volatile("ldmatrix.sync.aligned.m8n8.x4.shared.b16 {%0,%1,%2,%3}, [%4];"
                 : "=r"(r0), "=r"(r1), "=r"(r2), "=r"(r3) : "r"(a));
}

// ------------------------------------------------- merged pre-pass kernel
// blocks [0, 8192):  convert/concat A
// blocks [8192, 16384): transpose + convert W (gate-interleaved rows)
__global__ void prep(const float* __restrict__ x, const float* __restrict__ h,
                     const float* __restrict__ Wx, const float* __restrict__ Wh)
{
    __shared__ __half t[32][36];
    const int tid = threadIdx.x;

    if (blockIdx.x < 8192) {
        // ---- A part: one 256-thread block handles 2048 halves (1 row) ---
        int i = blockIdx.x * 256 + tid;
        int row = i >> 8;
        int col = (i & 255) * 8;
        const float* src = (col < 1024) ? (x + (size_t)row * 1024 + col)
                                        : (h + (size_t)row * 1024 + (col - 1024));
        float4 v0 = ((const float4*)src)[0];
        float4 v1 = ((const float4*)src)[1];
        __half2 p[4];
        p[0] = __floats2half2_rn(v0.x, v0.y);
        p[1] = __floats2half2_rn(v0.z, v0.w);
        p[2] = __floats2half2_rn(v1.x, v1.y);
        p[3] = __floats2half2_rn(v1.z, v1.w);
        *(uint4*)(g_Ah + (size_t)row * K_DIM + col) = *(uint4*)p;
    } else {
        // ---- W part: 32x32 transpose tile ------------------------------
        int idx = blockIdx.x - 8192;
        int g   = idx & 3;
        int rest = idx >> 2;
        int j0 = (rest & 31) * 32;
        int k0 = (rest >> 5) * 32;
        int tx = tid & 31, ty = tid >> 5;        // 32 x 8
        #pragma unroll
        for (int i = 0; i < 4; i++) {
            int k = k0 + ty + i * 8;
            const float* src = (k < 1024) ? (Wx + (size_t)k * N_DIM)
                                          : (Wh + (size_t)(k - 1024) * N_DIM);
            t[ty + i * 8][tx] = __float2half_rn(src[g * 1024 + j0 + tx]);
        }
        __syncthreads();
        #pragma unroll
        for (int i = 0; i < 4; i++) {
            int jj = ty + i * 8;
            g_Wt[((size_t)(j0 + jj) * 4 + g) * K_DIM + k0 + tx] = t[tx][jj];
        }
    }
}

// ------------------------------------------------------------- main kernel
__global__ __launch_bounds__(THREADS, 2)
void lstm_main(const float* __restrict__ cin, const float* __restrict__ bx,
               float* __restrict__ out)
{
    extern __shared__ char smem[];
    const uint32_t sb = smem_u32(smem);
    const int tid  = threadIdx.x;
    const int lane = tid & 31;
    const int warp = tid >> 5;
    const int wm   = warp >> 2;       // 0..1  (64-row slab)
    const int wn   = warp & 3;        // 0..3  (32-col slab)
    const int m0 = blockIdx.y * BM;
    const int n0 = blockIdx.x * BN;
    const int jt0 = n0 >> 2;

    const int r0 = tid >> 3, c8 = tid & 7;   // copy map: 32 rows x 8 x 16B

    const __half* Agm = g_Ah + (size_t)m0 * K_DIM;
    const __half* Bgm = g_Wt + (size_t)n0 * K_DIM;

    float acc[4][4][4];
    #pragma unroll
    for (int i = 0; i < 4; i++)
        #pragma unroll
        for (int j = 0; j < 4; j++)
            #pragma unroll
            for (int k = 0; k < 4; k++) acc[i][j][k] = 0.0f;

    // -- pipeline prologue: chunks 0,1 ------------------------------------
    #pragma unroll
    for (int pc = 0; pc < 2; pc++) {
        uint32_t Ab = sb + pc * STAGE_BYTES;
        uint32_t Bb = Ab + BM * 128;
        #pragma unroll
        for (int i = 0; i < 4; i++) {
            int row = r0 + 32 * i;
            uint32_t o = (uint32_t)row * 128 + c8 * 16;
            cp16(Ab + SW128(o), Agm + (size_t)row * K_DIM + pc * BKH + c8 * 8);
            cp16(Bb + SW128(o), Bgm + (size_t)row * K_DIM + pc * BKH + c8 * 8);
        }
        CP_COMMIT();
    }

    const int qq = lane >> 3;
    const int rr = lane & 7;

    // -- main loop: one barrier per chunk ---------------------------------
    for (int kt = 0; kt < NCHUNK; kt++) {
        if (kt + 1 < NCHUNK)
            asm volatile("cp.async.wait_group 1;" ::: "memory");
        else
            asm volatile("cp.async.wait_group 0;" ::: "memory");
        __syncthreads();

        if (kt + 2 < NCHUNK) {
            const int s = (kt + 2) % STAGES;
            uint32_t Ab = sb + s * STAGE_BYTES;
            uint32_t Bb = Ab + BM * 128;
            const int ko = (kt + 2) * BKH;
            #pragma unroll
            for (int i = 0; i < 4; i++) {
                int row = r0 + 32 * i;
                uint32_t o = (uint32_t)row * 128 + c8 * 16;
                cp16(Ab + SW128(o), Agm + (size_t)row * K_DIM + ko + c8 * 8);
                cp16(Bb + SW128(o), Bgm + (size_t)row * K_DIM + ko + c8 * 8);
            }
            CP_COMMIT();
        }

        // compute on stage kt%3, with ks-level A-fragment double buffering
        const uint32_t Ab = sb + (kt % STAGES) * STAGE_BYTES;
        const uint32_t Bb = Ab + BM * 128;

        uint32_t af[2][16];
        #pragma unroll
        for (int mt = 0; mt < 4; mt++) {       // preload ks=0 A frags
            int row = wm * 64 + mt * 16 + (qq & 1) * 8 + rr;
            uint32_t o = (uint32_t)row * 128 + (qq >> 1) * 16;
            ldsm4(af[0][mt * 4], af[0][mt * 4 + 1],
                  af[0][mt * 4 + 2], af[0][mt * 4 + 3], Ab + SW128(o));
        }

        #pragma unroll
        for (int ks = 0; ks < 4; ks++) {
            uint32_t b[2][4];
            #pragma unroll
            for (int np = 0; np < 2; np++) {   // B frags for this ks
                int row = wn * 32 + np * 16 + (qq >> 1) * 8 + rr;
                uint32_t o = (uint32_t)row * 128 + ks * 32 + (qq & 1) * 16;
                ldsm4(b[np][0], b[np][1], b[np][2], b[np][3], Bb + SW128(o));
            }
            if (ks < 3) {                      // prefetch next ks A frags
                #pragma unroll
                for (int mt = 0; mt < 4; mt++) {
                    int row = wm * 64 + mt * 16 + (qq & 1) * 8 + rr;
                    uint32_t o = (uint32_t)row * 128 + (ks + 1) * 32
                                 + (qq >> 1) * 16;
                    ldsm4(af[(ks + 1) & 1][mt * 4], af[(ks + 1) & 1][mt * 4 + 1],
                          af[(ks + 1) & 1][mt * 4 + 2], af[(ks + 1) & 1][mt * 4 + 3],
                          Ab + SW128(o));
                }
            }
            const uint32_t* ac = af[ks & 1];
            #pragma unroll
            for (int mt = 0; mt < 4; mt++)
                #pragma unroll
                for (int nt = 0; nt < 4; nt++) {
                    const uint32_t b0 = b[nt >> 1][(nt & 1) * 2];
                    const uint32_t b1 = b[nt >> 1][(nt & 1) * 2 + 1];
                    asm volatile(
                        "mma.sync.aligned.m16n8k16.row.col.f32.f16.f16.f32 "
                        "{%0,%1,%2,%3}, {%4,%5,%6,%7}, {%8,%9}, {%0,%1,%2,%3};"
                        : "+f"(acc[mt][nt][0]), "+f"(acc[mt][nt][1]),
                          "+f"(acc[mt][nt][2]), "+f"(acc[mt][nt][3])
                        : "r"(ac[mt * 4]), "r"(ac[mt * 4 + 1]),
                          "r"(ac[mt * 4 + 2]), "r"(ac[mt * 4 + 3]),
                          "r"(b0), "r"(b1));
                }
        }
    }
    __syncthreads();   // retire last compute before smem reuse (epilogue)

    // -- epilogue: regroup via smem, fuse LSTM ----------------------------
    float* gsm = (float*)smem;        // [128][LDE]
    {
        const int gr = lane >> 2, gc = lane & 3;
        #pragma unroll
        for (int mt = 0; mt < 4; mt++)
            #pragma unroll
            for (int nt = 0; nt < 4; nt++) {
                int row = wm * 64 + mt * 16 + gr;
                int col = wn * 32 + nt * 8 + gc * 2;
                *(float2*)&gsm[row * LDE + col] =
                    make_float2(acc[mt][nt][0], acc[mt][nt][1]);
                *(float2*)&gsm[(row + 8) * LDE + col] =
                    make_float2(acc[mt][nt][2], acc[mt][nt][3]);
            }
    }
    float* bsm = (float*)(smem + OFF_BIAS);
    if (tid < BN)
        bsm[tid] = bx[(tid & 3) * 1024 + jt0 + (tid >> 2)];
    __syncthreads();

    float* outh = out;
    float* outc = out + (size_t)B_DIM * H_DIM;
    #pragma unroll
    for (int i = 0; i < 16; i++) {
        int o   = tid + i * THREADS;   // 0..4095 = 128 rows x 32 units
        int u   = o & 31;
        int row = o >> 5;
        float4 g4 = *(const float4*)&gsm[row * LDE + u * 4];
        float4 b4 = *(const float4*)&bsm[u * 4];
        float gi = g4.x + b4.x;
        float gf = g4.y + b4.y;
        float gg = g4.z + b4.z;
        float go = g4.w + b4.w;
        float iv = 1.0f / (1.0f + __expf(-gi));
        float fv = 1.0f / (1.0f + __expf(-gf));
        float gv = tanhf(gg);
        float ov = 1.0f / (1.0f + __expf(-go));
        size_t gidx = (size_t)(m0 + row) * H_DIM + jt0 + u;
        float cn = fv * cin[gidx] + iv * gv;
        outh[gidx] = ov * tanhf(cn);
        outc[gidx] = cn;
    }
}

// ------------------------------------------------------------- launch
extern "C" void kernel_launch(void* const* d_in, const int* in_sizes, int n_in,
                              void* d_out, int out_size)
{
    const float* x  = (const float*)d_in[0];
    const float* h  = (const float*)d_in[1];
    const float* c  = (const float*)d_in[2];
    const float* Wx = (const float*)d_in[3];
    const float* bx = (const float*)d_in[4];
    const float* Wh = (const float*)d_in[5];
    float* out = (float*)d_out;

    prep<<<16384, 256>>>(x, h, Wx, Wh);

    cudaFuncSetAttribute(lstm_main,
                         cudaFuncAttributeMaxDynamicSharedMemorySize, SMEM_TOTAL);
    dim3 grid(N_DIM / BN, B_DIM / BM);   // (32, 64)
    lstm_main<<<grid, THREADS, SMEM_TOTAL>>>(c, bx, out);
}